// round 3
// baseline (speedup 1.0000x reference)
#include <cuda_runtime.h>

#define NS  12
#define NC  4
#define TT  50
#define BB  2048
#define NLS 5
#define WPB 2

__device__ float g_taus[NLS * TT * BB * 16];  // [a][t][b][16]

// ---- per-warp smem layout (float offsets) ----
#define OFF_F    0      // 240 (riccati stride16 uses 192; rollout stride20 uses 240)
// union region @240 (576 floats)
#define OFF_V    240    // 144, stride 12
#define OFF_v    384    // 16
#define OFF_QUU  400    // 16
#define OFF_QXU  416    // 48
#define OFF_MB   464    // 156, stride 13
#define OFF_C    240    // 320, stride 20 (rollout)
#define OFF_c    560    // 16
#define OFF_f    576    // 16
#define OFF_TAU  592    // 80
#define OFF_PART 672    // 80
#define OFF_X    752    // 64
#define OFF_K    816    // 2600 = 50*52, layout [t][ s*4+u ], kk at 48+u
#define OFF_UN   3416   // 200
#define WF       3616

// ---------------- Riccati prefetch ----------------
struct RP {
    float  Cc[8];          // C column j, rows h*8+ii
    float4 F0, F1;         // row-major chunks (for smem commit)
    float  Fc[12];         // F column j
    float  cj;
    float4 f0, f1, f2;     // f broadcast
};

__device__ __forceinline__ void r_load(RP& p,
    const float* __restrict__ gC, const float* __restrict__ gc,
    const float* __restrict__ gF, const float* __restrict__ gf,
    int base, int lane, int h, int j)
{
    const float* Cb = gC + (size_t)base * 256;
#pragma unroll
    for (int ii = 0; ii < 8; ++ii) p.Cc[ii] = Cb[(h * 8 + ii) * 16 + j];
    const float4* F4 = reinterpret_cast<const float4*>(gF) + (size_t)base * 48;
    p.F0 = F4[lane];
    if (lane < 16) p.F1 = F4[lane + 32];
    const float* Fb = gF + (size_t)base * 192;
#pragma unroll
    for (int m = 0; m < 12; ++m) p.Fc[m] = Fb[m * 16 + j];
    p.cj = gc[(size_t)base * 16 + j];
    const float4* fb = reinterpret_cast<const float4*>(gf + (size_t)base * 12);
    p.f0 = fb[0]; p.f1 = fb[1]; p.f2 = fb[2];
}

// ---------------- rollout prefetch ----------------
struct FP { float4 C0, C1, F0, F1, c4, f0, f1, f2; };

__device__ __forceinline__ void f_load(FP& p,
    const float* __restrict__ gC, const float* __restrict__ gc,
    const float* __restrict__ gF, const float* __restrict__ gf,
    int base, int lane)
{
    const float4* C4 = reinterpret_cast<const float4*>(gC) + (size_t)base * 64;
    p.C0 = C4[lane];
    p.C1 = C4[lane + 32];
    const float4* F4 = reinterpret_cast<const float4*>(gF) + (size_t)base * 48;
    p.F0 = F4[lane];
    if (lane < 16) p.F1 = F4[lane + 32];
    if (lane < 4)  p.c4 = reinterpret_cast<const float4*>(gc)[(size_t)base * 4 + lane];
    const float4* fb = reinterpret_cast<const float4*>(gf + (size_t)base * 12);
    p.f0 = fb[0]; p.f1 = fb[1]; p.f2 = fb[2];
}

__global__ void __launch_bounds__(32 * WPB) ilqr_fused_kernel(
    const float* __restrict__ gC, const float* __restrict__ gc,
    const float* __restrict__ gF, const float* __restrict__ gf,
    const float* __restrict__ gx0, float* __restrict__ out)
{
    __shared__ __align__(16) float smem[WPB][WF];
    const int w    = threadIdx.x >> 5;
    const int lane = threadIdx.x & 31;
    const int b    = blockIdx.x * WPB + w;
    const int j    = lane & 15;
    const int h    = lane >> 4;

    float* S = smem[w];
    float* sF  = S + OFF_F;
    float* sV  = S + OFF_V;
    float* sv  = S + OFF_v;
    float* sQuu = S + OFF_QUU;
    float* sQxu = S + OFF_QXU;
    float* sMb  = S + OFF_MB;
    float* sC   = S + OFF_C;
    float* sc_  = S + OFF_c;
    float* sf_  = S + OFF_f;
    float* sTau = S + OFF_TAU;
    float* sPart= S + OFF_PART;
    float* sX   = S + OFF_X;
    float* sKall= S + OFF_K;
    float* sUn  = S + OFF_UN;

    for (int idx = lane; idx < 200; idx += 32) sUn[idx] = 0.f;

    for (int it = 0; it < 3; ++it) {
        const bool final_it = (it == 2);

        // ======================= Backward Riccati =======================
        for (int idx = lane; idx < 144; idx += 32) sV[idx] = 0.f;
        if (lane < 12) sv[lane] = 0.f;

        RP cur, nxt;
        r_load(cur, gC, gc, gF, gf, (TT - 1) * BB + b, lane, h, j);

        for (int t = TT - 1; t >= 0; --t) {
            // commit F rows (stride 16)
            reinterpret_cast<float4*>(sF)[lane] = cur.F0;
            if (lane < 16) reinterpret_cast<float4*>(sF)[lane + 32] = cur.F1;
            __syncwarp();
            if (t > 0) r_load(nxt, gC, gc, gF, gf, (t - 1) * BB + b, lane, h, j);

            // ---- Phase 1: W rows (h*6+kk) of col j, g = (Vf+v) rows h*6+kk
            float W6[6], g6[6];
#pragma unroll
            for (int kk = 0; kk < 6; ++kk) {
                int row = h * 6 + kk;
                const float4* vr = reinterpret_cast<const float4*>(sV + row * 12);
                float4 a0 = vr[0], a1 = vr[1], a2 = vr[2];
                W6[kk] = a0.x*cur.Fc[0] + a0.y*cur.Fc[1] + a0.z*cur.Fc[2] + a0.w*cur.Fc[3]
                       + a1.x*cur.Fc[4] + a1.y*cur.Fc[5] + a1.z*cur.Fc[6] + a1.w*cur.Fc[7]
                       + a2.x*cur.Fc[8] + a2.y*cur.Fc[9] + a2.z*cur.Fc[10]+ a2.w*cur.Fc[11];
                g6[kk] = a0.x*cur.f0.x + a0.y*cur.f0.y + a0.z*cur.f0.z + a0.w*cur.f0.w
                       + a1.x*cur.f1.x + a1.y*cur.f1.y + a1.z*cur.f1.z + a1.w*cur.f1.w
                       + a2.x*cur.f2.x + a2.y*cur.f2.y + a2.z*cur.f2.z + a2.w*cur.f2.w
                       + sv[row];
            }
            // q[j] = c[j] + sum_k F[k][j] * g[k]
            float pj = 0.f;
#pragma unroll
            for (int kk = 0; kk < 6; ++kk) pj += cur.Fc[h * 6 + kk] * g6[kk];
            float qj = cur.cj + pj + __shfl_xor_sync(0xffffffffu, pj, 16);

            // ---- Phase 2: Q[h*8+ii][j] = C + sum_k F[k][h*8+ii] W[k][j]
            float Qc[8];
#pragma unroll
            for (int ii = 0; ii < 8; ++ii) Qc[ii] = cur.Cc[ii];
            float wlo[6], whi[6];
#pragma unroll
            for (int kk = 0; kk < 6; ++kk) {
                float o = __shfl_xor_sync(0xffffffffu, W6[kk], 16);
                wlo[kk] = h ? o : W6[kk];
                whi[kk] = h ? W6[kk] : o;
            }
#pragma unroll
            for (int k = 0; k < 12; ++k) {
                float wk = (k < 6) ? wlo[k] : whi[k - 6];
                const float4* fr = reinterpret_cast<const float4*>(sF + k * 16 + h * 8);
                float4 fa = fr[0], fb2 = fr[1];
                Qc[0] += fa.x * wk;  Qc[1] += fa.y * wk;
                Qc[2] += fa.z * wk;  Qc[3] += fa.w * wk;
                Qc[4] += fb2.x * wk; Qc[5] += fb2.y * wk;
                Qc[6] += fb2.z * wk; Qc[7] += fb2.w * wk;
            }

            // ---- stage Quu / Qxu
            if (j >= 12) {
                int w2 = j - 12;
                if (h == 1) {
#pragma unroll
                    for (int u = 0; u < 4; ++u) sQuu[u * 4 + w2] = Qc[4 + u];
#pragma unroll
                    for (int ii = 0; ii < 4; ++ii) sQxu[(8 + ii) * 4 + w2] = Qc[ii];
                } else {
#pragma unroll
                    for (int ii = 0; ii < 8; ++ii) sQxu[ii * 4 + w2] = Qc[ii];
                }
            }
            __syncwarp();

            // ---- Phase 3: solve
            float qu[4];
#pragma unroll
            for (int u = 0; u < 4; ++u) qu[u] = __shfl_sync(0xffffffffu, qj, 12 + u);
            float t6 = __shfl_xor_sync(0xffffffffu, Qc[6], 16);
            float t7 = __shfl_xor_sync(0xffffffffu, Qc[7], 16);
            float r[4];
#pragma unroll
            for (int u = 0; u < 4; ++u) {
                float o  = __shfl_xor_sync(0xffffffffu, Qc[4 + u], 16);
                float rx = h ? Qc[4 + u] : o;     // Q[12+u][j]
                r[u] = (j < 12) ? rx : qu[u];
            }
            float4 A0 = *reinterpret_cast<const float4*>(sQuu + 0);
            float4 A1 = *reinterpret_cast<const float4*>(sQuu + 4);
            float4 A2 = *reinterpret_cast<const float4*>(sQuu + 8);
            float4 A3 = *reinterpret_cast<const float4*>(sQuu + 12);
            float A[4][4] = {{A0.x,A0.y,A0.z,A0.w},{A1.x,A1.y,A1.z,A1.w},
                             {A2.x,A2.y,A2.z,A2.w},{A3.x,A3.y,A3.z,A3.w}};
#pragma unroll
            for (int pp = 0; pp < 4; ++pp) {
                float inv = 1.0f / A[pp][pp];
                r[pp] *= inv;
#pragma unroll
                for (int w2 = 0; w2 < 4; ++w2) if (w2 > pp) A[pp][w2] *= inv;
#pragma unroll
                for (int u = 0; u < 4; ++u) if (u > pp) {
                    float mu = A[u][pp];
                    r[u] -= mu * r[pp];
#pragma unroll
                    for (int w2 = 0; w2 < 4; ++w2) if (w2 > pp) A[u][w2] -= mu * A[pp][w2];
                }
            }
#pragma unroll
            for (int pp = 3; pp >= 1; --pp)
#pragma unroll
                for (int u = 0; u < 4; ++u) if (u < pp) r[u] -= A[u][pp] * r[pp];

            float K4[4];
#pragma unroll
            for (int u = 0; u < 4; ++u) K4[u] = -r[u];

            float* sKt = sKall + t * 52;
            if (lane < 12) {
                *reinterpret_cast<float4*>(sKt + j * 4) = make_float4(K4[0], K4[1], K4[2], K4[3]);
            } else if (lane == 12) {
                *reinterpret_cast<float4*>(sKt + 48) = make_float4(K4[0], K4[1], K4[2], K4[3]);
            }

            // ---- Phase 4: M col j rows h*6+kk; symmetrize; v_new
            float Mi[6];
            if (j < 12) {
#pragma unroll
                for (int kk = 0; kk < 6; ++kk) {
                    int i = h * 6 + kk;
                    float qij;
                    if (h == 0) qij = Qc[kk];
                    else        qij = (kk == 0) ? t6 : ((kk == 1) ? t7 : Qc[kk - 2]);
                    float4 x4 = *reinterpret_cast<const float4*>(sQxu + i * 4);
                    Mi[kk] = qij + x4.x*K4[0] + x4.y*K4[1] + x4.z*K4[2] + x4.w*K4[3];
                }
#pragma unroll
                for (int kk = 0; kk < 6; ++kk) sMb[(h * 6 + kk) * 13 + j] = Mi[kk];
            }
            __syncwarp();
            if (j < 12) {
#pragma unroll
                for (int kk = 0; kk < 6; ++kk) {
                    int i = h * 6 + kk;
                    sV[i * 12 + j] = 0.5f * (Mi[kk] + sMb[j * 13 + i]);
                }
                if (h == 0)
                    sv[j] = qj + K4[0]*qu[0] + K4[1]*qu[1] + K4[2]*qu[2] + K4[3]*qu[3];
            }
            cur = nxt;
            __syncwarp();
        }

        // ======================= Forward rollout =======================
        if (lane < 12) {
            float x = gx0[b * 12 + lane];
#pragma unroll
            for (int a = 0; a < 5; ++a) sX[a * 12 + lane] = x;
        }
        float myCost = 0.f;

        FP p, pn;
        f_load(p, gC, gc, gF, gf, 0 * BB + b, lane);

        for (int t = 0; t < TT; ++t) {
            // commit (stride 20)
            {
                int r0 = lane >> 2, c0 = (lane & 3) * 4;
                *reinterpret_cast<float4*>(sC + r0 * 20 + c0)       = p.C0;
                *reinterpret_cast<float4*>(sC + (8 + r0) * 20 + c0) = p.C1;
                *reinterpret_cast<float4*>(sF + r0 * 20 + c0)       = p.F0;
                if (lane < 16) {
                    int r1 = 8 + (lane >> 2);
                    *reinterpret_cast<float4*>(sF + r1 * 20 + c0)   = p.F1;
                }
                if (lane < 4) *reinterpret_cast<float4*>(sc_ + lane * 4) = p.c4;
                if (lane == 0) {
                    *reinterpret_cast<float4*>(sf_)     = p.f0;
                    *reinterpret_cast<float4*>(sf_ + 4) = p.f1;
                    *reinterpret_cast<float4*>(sf_ + 8) = p.f2;
                }
            }
            __syncwarp();
            if (t < TT - 1) f_load(pn, gC, gc, gF, gf, (t + 1) * BB + b, lane);

            const float* sKt = sKall + t * 52;

            // controls: lane = a*4+u (lane<20)
            if (lane < 20) {
                int a = lane >> 2, u = lane & 3;
                float ul = sKt[48 + u];
#pragma unroll
                for (int s = 0; s < 12; ++s) ul += sKt[s * 4 + u] * sX[a * 12 + s];
                float alpha = 1.0f / (float)(1 << a);
                float uu = (1.0f - alpha) * sUn[t * 4 + u] + alpha * ul;
                uu = fminf(1.0f, fmaxf(-1.0f, uu));
                sTau[a * 16 + 12 + u] = uu;
            }
#pragma unroll
            for (int rr = 0; rr < 2; ++rr) {
                int idx = lane + 32 * rr;
                if (idx < 60) {
                    int a = idx / 12, s = idx - a * 12;
                    sTau[a * 16 + s] = sX[idx];
                }
            }
            __syncwarp();

            // cost partials (C symmetric: row read) + taus writes
#pragma unroll
            for (int rr = 0; rr < 3; ++rr) {
                int idx = lane + 32 * rr;
                if (idx < 80) {
                    int a = idx >> 4, jj = idx & 15;
                    const float4* cr = reinterpret_cast<const float4*>(sC + jj * 20);
                    const float4* tr = reinterpret_cast<const float4*>(sTau + a * 16);
                    float s = 0.f;
#pragma unroll
                    for (int iv = 0; iv < 4; ++iv) {
                        float4 cc = cr[iv], tt = tr[iv];
                        s += cc.x*tt.x + cc.y*tt.y + cc.z*tt.z + cc.w*tt.w;
                    }
                    float ta = sTau[a * 16 + jj];
                    sPart[idx] = ta * (0.5f * s + sc_[jj]);
                    if (final_it || jj >= 12)
                        g_taus[((size_t)(a * TT + t) * BB + b) * 16 + jj] = ta;
                }
            }
            // x_next
            float xn0 = 0.f, xn1 = 0.f;
            {
                int idx = lane;
                if (idx < 60) {
                    int a = idx / 12, s = idx - a * 12;
                    const float4* fr4 = reinterpret_cast<const float4*>(sF + s * 20);
                    const float4* tr  = reinterpret_cast<const float4*>(sTau + a * 16);
                    float v = sf_[s];
#pragma unroll
                    for (int iv = 0; iv < 4; ++iv) {
                        float4 ff = fr4[iv], tt = tr[iv];
                        v += ff.x*tt.x + ff.y*tt.y + ff.z*tt.z + ff.w*tt.w;
                    }
                    xn0 = v;
                }
                idx = lane + 32;
                if (idx < 60) {
                    int a = idx / 12, s = idx - a * 12;
                    const float4* fr4 = reinterpret_cast<const float4*>(sF + s * 20);
                    const float4* tr  = reinterpret_cast<const float4*>(sTau + a * 16);
                    float v = sf_[s];
#pragma unroll
                    for (int iv = 0; iv < 4; ++iv) {
                        float4 ff = fr4[iv], tt = tr[iv];
                        v += ff.x*tt.x + ff.y*tt.y + ff.z*tt.z + ff.w*tt.w;
                    }
                    xn1 = v;
                }
            }
            __syncwarp();

            if (lane < 5) {
                const float4* pr = reinterpret_cast<const float4*>(sPart + lane * 16);
                float cs = 0.f;
#pragma unroll
                for (int iv = 0; iv < 4; ++iv) {
                    float4 pp = pr[iv];
                    cs += pp.x + pp.y + pp.z + pp.w;
                }
                myCost += cs;
            }
            if (lane < 60) sX[lane] = xn0;
            if (lane + 32 < 60) sX[lane + 32] = xn1;
            p = pn;
            __syncwarp();
        }
        __syncwarp();

        // argmin over alphas (first-min)
        int bi = 0;
        {
            float bc = __shfl_sync(0xffffffffu, myCost, 0);
#pragma unroll
            for (int a = 1; a < NLS; ++a) {
                float ca = __shfl_sync(0xffffffffu, myCost, a);
                if (ca < bc) { bc = ca; bi = a; }
            }
        }

        if (!final_it) {
            for (int idx = lane; idx < 200; idx += 32) {
                int t = idx >> 2, u = idx & 3;
                sUn[idx] = g_taus[((size_t)(bi * TT + t) * BB + b) * 16 + 12 + u];
            }
        } else {
            for (int idx = lane; idx < 800; idx += 32) {
                int t = idx >> 4, i = idx & 15;
                out[((size_t)t * BB + b) * 16 + i] =
                    g_taus[((size_t)(bi * TT + t) * BB + b) * 16 + i];
            }
        }
        __syncwarp();
    }
}

extern "C" void kernel_launch(void* const* d_in, const int* in_sizes, int n_in,
                              void* d_out, int out_size)
{
    const float *x0 = nullptr, *C = nullptr, *c = nullptr, *F = nullptr, *f = nullptr;
    for (int i = 0; i < n_in; ++i) {
        switch (in_sizes[i]) {
            case BB * NS:            x0 = (const float*)d_in[i]; break;
            case TT * BB * 256:      C  = (const float*)d_in[i]; break;
            case TT * BB * 16:       c  = (const float*)d_in[i]; break;
            case TT * BB * 192:      F  = (const float*)d_in[i]; break;
            case TT * BB * NS:       f  = (const float*)d_in[i]; break;
        }
    }
    ilqr_fused_kernel<<<BB / WPB, 32 * WPB>>>(C, c, F, f, x0, (float*)d_out);
}

// round 4
// speedup vs baseline: 1.5390x; 1.5390x over previous
#include <cuda_runtime.h>

#define TT  50
#define BB  2048
#define NLS 5
#define WPB 2

__device__ float g_taus[NLS * TT * BB * 16];  // [a][t][b][16]

// ---- per-warp smem layout (float offsets) ----
#define OFF_F    0      // 240 (riccati stride16: 192; rollout stride20: 240)
#define OFF_V    240    // 144, stride 12   (riccati)
#define OFF_v    384    // 16
#define OFF_QXU  416    // 32  (Qxu rows 0-7, stride 4; base bank 0)
#define OFF_QXB  464    // 16  (Qxu rows 8-11; base bank 16)
#define OFF_QUU  480    // 16  (base bank 0)
#define OFF_MB   496    // 156, stride 13 (base bank 16)
#define OFF_RF   656    // 16  (riccati f)
#define OFF_C    240    // 320, stride 20 (rollout)
#define OFF_c    560    // 16  (rollout)
#define OFF_f    576    // 16  (rollout)
#define OFF_TAU  592    // 80
#define OFF_PART 672    // 80
#define OFF_X    752    // 64
#define OFF_K    816    // 2600 = 50*52: [t][s*4+u], kk at 48+u
#define OFF_UN   3416   // 200
#define WF       3616

// ---------------- Riccati prefetch (single buffer, ~21 regs) --------------
struct RPre { float4 F0, F1, f4, ca, cb; float cj; };

__device__ __forceinline__ void r_load(RPre& p,
    const float* __restrict__ gC, const float* __restrict__ gc,
    const float* __restrict__ gF, const float* __restrict__ gf,
    int base, int lane, int h, int j)
{
    const float4* F4 = reinterpret_cast<const float4*>(gF) + (size_t)base * 48;
    p.F0 = F4[lane];
    if (lane < 16) p.F1 = F4[lane + 32];
    // lane (h,j) takes C[j][h*8 .. h*8+7]  (C is symmetric: col j == row j)
    const float4* C4 = reinterpret_cast<const float4*>(gC) + (size_t)base * 64;
    p.ca = C4[j * 4 + h * 2];
    p.cb = C4[j * 4 + h * 2 + 1];
    p.cj = gc[(size_t)base * 16 + j];
    if (lane < 3) p.f4 = reinterpret_cast<const float4*>(gf + (size_t)base * 12)[lane];
}

// ---------------- rollout prefetch (single buffer, ~24 regs) --------------
struct FPre { float4 C0, C1, F0, F1, c4, f4; };

__device__ __forceinline__ void f_load(FPre& p,
    const float* __restrict__ gC, const float* __restrict__ gc,
    const float* __restrict__ gF, const float* __restrict__ gf,
    int base, int lane)
{
    const float4* C4 = reinterpret_cast<const float4*>(gC) + (size_t)base * 64;
    p.C0 = C4[lane];
    p.C1 = C4[lane + 32];
    const float4* F4 = reinterpret_cast<const float4*>(gF) + (size_t)base * 48;
    p.F0 = F4[lane];
    if (lane < 16) p.F1 = F4[lane + 32];
    if (lane < 4)  p.c4 = reinterpret_cast<const float4*>(gc)[(size_t)base * 4 + lane];
    if (lane < 3)  p.f4 = reinterpret_cast<const float4*>(gf + (size_t)base * 12)[lane];
}

__global__ void __launch_bounds__(32 * WPB, 7) ilqr_fused_kernel(
    const float* __restrict__ gC, const float* __restrict__ gc,
    const float* __restrict__ gF, const float* __restrict__ gf,
    const float* __restrict__ gx0, float* __restrict__ out)
{
    __shared__ __align__(16) float smem[WPB][WF];
    const int w    = threadIdx.x >> 5;
    const int lane = threadIdx.x & 31;
    const int b    = blockIdx.x * WPB + w;
    const int j    = lane & 15;
    const int h    = lane >> 4;

    float* S = smem[w];
    float* sF   = S + OFF_F;
    float* sV   = S + OFF_V;
    float* sv   = S + OFF_v;
    float* sQxu = S + OFF_QXU;
    float* sQxB = S + OFF_QXB;
    float* sQuu = S + OFF_QUU;
    float* sMb  = S + OFF_MB;
    float* sRf  = S + OFF_RF;
    float* sC   = S + OFF_C;
    float* sc_  = S + OFF_c;
    float* sf_  = S + OFF_f;
    float* sTau = S + OFF_TAU;
    float* sPart= S + OFF_PART;
    float* sX   = S + OFF_X;
    float* sKall= S + OFF_K;
    float* sUn  = S + OFF_UN;

    for (int idx = lane; idx < 200; idx += 32) sUn[idx] = 0.f;

    for (int it = 0; it < 3; ++it) {
        const bool final_it = (it == 2);

        // ======================= Backward Riccati =======================
        for (int idx = lane; idx < 144; idx += 32) sV[idx] = 0.f;
        if (lane < 12) sv[lane] = 0.f;

        RPre p;
        r_load(p, gC, gc, gF, gf, (TT - 1) * BB + b, lane, h, j);

        for (int t = TT - 1; t >= 0; --t) {
            // commit F (stride 16) and f; move C/c to working regs
            reinterpret_cast<float4*>(sF)[lane] = p.F0;
            if (lane < 16) reinterpret_cast<float4*>(sF)[lane + 32] = p.F1;
            if (lane < 3)  reinterpret_cast<float4*>(sRf)[lane] = p.f4;
            float Qc[8] = {p.ca.x, p.ca.y, p.ca.z, p.ca.w,
                           p.cb.x, p.cb.y, p.cb.z, p.cb.w};
            const float cj = p.cj;
            __syncwarp();
            if (t > 0) r_load(p, gC, gc, gF, gf, (t - 1) * BB + b, lane, h, j);

            // F column j (registers, reused phase1 + q)
            float Fc[12];
#pragma unroll
            for (int m = 0; m < 12; ++m) Fc[m] = sF[m * 16 + j];

            // f broadcast
            const float4 fv0 = *reinterpret_cast<const float4*>(sRf);
            const float4 fv1 = *reinterpret_cast<const float4*>(sRf + 4);
            const float4 fv2 = *reinterpret_cast<const float4*>(sRf + 8);

            // ---- Phase 1: W[h*6+kk][j] = (V F)_col-j ; g = V f + v
            float W6[6], qj;
            {
                float g6[6];
#pragma unroll
                for (int kk = 0; kk < 6; ++kk) {
                    const int row = h * 6 + kk;
                    const float4* vr = reinterpret_cast<const float4*>(sV + row * 12);
                    const float4 a0 = vr[0], a1 = vr[1], a2 = vr[2];
                    W6[kk] = a0.x*Fc[0] + a0.y*Fc[1] + a0.z*Fc[2] + a0.w*Fc[3]
                           + a1.x*Fc[4] + a1.y*Fc[5] + a1.z*Fc[6] + a1.w*Fc[7]
                           + a2.x*Fc[8] + a2.y*Fc[9] + a2.z*Fc[10]+ a2.w*Fc[11];
                    g6[kk] = a0.x*fv0.x + a0.y*fv0.y + a0.z*fv0.z + a0.w*fv0.w
                           + a1.x*fv1.x + a1.y*fv1.y + a1.z*fv1.z + a1.w*fv1.w
                           + a2.x*fv2.x + a2.y*fv2.y + a2.z*fv2.z + a2.w*fv2.w
                           + sv[row];
                }
                float pj = 0.f;
#pragma unroll
                for (int kk = 0; kk < 6; ++kk) pj += Fc[h * 6 + kk] * g6[kk];
                qj = cj + pj + __shfl_xor_sync(0xffffffffu, pj, 16);
            }

            // ---- Phase 2: Qc[ii] += sum_k F[k][h*8+ii] * W[k][j]
            {
                float wlo[6], whi[6];
#pragma unroll
                for (int kk = 0; kk < 6; ++kk) {
                    const float o = __shfl_xor_sync(0xffffffffu, W6[kk], 16);
                    wlo[kk] = h ? o : W6[kk];
                    whi[kk] = h ? W6[kk] : o;
                }
#pragma unroll
                for (int k = 0; k < 12; ++k) {
                    const float wk = (k < 6) ? wlo[k] : whi[k - 6];
                    const float4* fr = reinterpret_cast<const float4*>(sF + k * 16 + h * 8);
                    const float4 fa = fr[0], fb2 = fr[1];
                    Qc[0] += fa.x * wk;  Qc[1] += fa.y * wk;
                    Qc[2] += fa.z * wk;  Qc[3] += fa.w * wk;
                    Qc[4] += fb2.x * wk; Qc[5] += fb2.y * wk;
                    Qc[6] += fb2.z * wk; Qc[7] += fb2.w * wk;
                }
            }

            // ---- stage Quu / Qxu (bank-disjoint: A bank0, B bank16, QUU bank0)
            if (j >= 12) {
                const int w2 = j - 12;
#pragma unroll
                for (int ii = 0; ii < 8; ++ii) {
                    float* dst;
                    if (h == 0)       dst = sQxu + ii * 4 + w2;
                    else if (ii < 4)  dst = sQxB + ii * 4 + w2;
                    else              dst = sQuu + (ii - 4) * 4 + w2;
                    *dst = Qc[ii];
                }
            }
            __syncwarp();

            // ---- Phase 3: solve Quu * sol = [Qux | qu], K = -sol
            float K4[4], qu[4], t6, t7;
            {
#pragma unroll
                for (int u = 0; u < 4; ++u) qu[u] = __shfl_sync(0xffffffffu, qj, 12 + u);
                t6 = __shfl_xor_sync(0xffffffffu, Qc[6], 16);
                t7 = __shfl_xor_sync(0xffffffffu, Qc[7], 16);
                float r[4];
#pragma unroll
                for (int u = 0; u < 4; ++u) {
                    const float o  = __shfl_xor_sync(0xffffffffu, Qc[4 + u], 16);
                    const float rx = h ? Qc[4 + u] : o;   // Q[12+u][j]
                    r[u] = (j < 12) ? rx : qu[u];
                }
                const float4 A0 = *reinterpret_cast<const float4*>(sQuu + 0);
                const float4 A1 = *reinterpret_cast<const float4*>(sQuu + 4);
                const float4 A2 = *reinterpret_cast<const float4*>(sQuu + 8);
                const float4 A3 = *reinterpret_cast<const float4*>(sQuu + 12);
                float A[4][4] = {{A0.x,A0.y,A0.z,A0.w},{A1.x,A1.y,A1.z,A1.w},
                                 {A2.x,A2.y,A2.z,A2.w},{A3.x,A3.y,A3.z,A3.w}};
#pragma unroll
                for (int pp = 0; pp < 4; ++pp) {
                    const float inv = 1.0f / A[pp][pp];
                    r[pp] *= inv;
#pragma unroll
                    for (int w2 = 0; w2 < 4; ++w2) if (w2 > pp) A[pp][w2] *= inv;
#pragma unroll
                    for (int u = 0; u < 4; ++u) if (u > pp) {
                        const float mu = A[u][pp];
                        r[u] -= mu * r[pp];
#pragma unroll
                        for (int w2 = 0; w2 < 4; ++w2) if (w2 > pp) A[u][w2] -= mu * A[pp][w2];
                    }
                }
#pragma unroll
                for (int pp = 3; pp >= 1; --pp)
#pragma unroll
                    for (int u = 0; u < 4; ++u) if (u < pp) r[u] -= A[u][pp] * r[pp];
#pragma unroll
                for (int u = 0; u < 4; ++u) K4[u] = -r[u];
            }

            float* sKt = sKall + t * 52;
            if (lane < 12)
                *reinterpret_cast<float4*>(sKt + j * 4) = make_float4(K4[0], K4[1], K4[2], K4[3]);
            else if (lane == 12)
                *reinterpret_cast<float4*>(sKt + 48) = make_float4(K4[0], K4[1], K4[2], K4[3]);

            // ---- Phase 4: M col j; symmetrize into V; v_new
            float Mi[6];
            if (j < 12) {
#pragma unroll
                for (int kk = 0; kk < 6; ++kk) {
                    const int i = h * 6 + kk;
                    float qij;
                    if (h == 0) qij = Qc[kk];
                    else        qij = (kk == 0) ? t6 : ((kk == 1) ? t7 : Qc[kk - 2]);
                    const float* xp = (i < 8) ? (sQxu + i * 4) : (sQxB + (i - 8) * 4);
                    const float4 x4 = *reinterpret_cast<const float4*>(xp);
                    Mi[kk] = qij + x4.x*K4[0] + x4.y*K4[1] + x4.z*K4[2] + x4.w*K4[3];
                }
#pragma unroll
                for (int kk = 0; kk < 6; ++kk) sMb[(h * 6 + kk) * 13 + j] = Mi[kk];
            }
            __syncwarp();
            if (j < 12) {
#pragma unroll
                for (int kk = 0; kk < 6; ++kk) {
                    const int i = h * 6 + kk;
                    sV[i * 12 + j] = 0.5f * (Mi[kk] + sMb[j * 13 + i]);
                }
                if (h == 0)
                    sv[j] = qj + K4[0]*qu[0] + K4[1]*qu[1] + K4[2]*qu[2] + K4[3]*qu[3];
            }
            __syncwarp();
        }

        // ======================= Forward rollout =======================
        if (lane < 12) {
            const float x = gx0[b * 12 + lane];
#pragma unroll
            for (int a = 0; a < 5; ++a) sX[a * 12 + lane] = x;
        }
        float myCost = 0.f;

        FPre q2;
        f_load(q2, gC, gc, gF, gf, 0 * BB + b, lane);

        for (int t = 0; t < TT; ++t) {
            // commit (stride 20)
            {
                const int r0 = lane >> 2, c0 = (lane & 3) * 4;
                *reinterpret_cast<float4*>(sC + r0 * 20 + c0)       = q2.C0;
                *reinterpret_cast<float4*>(sC + (8 + r0) * 20 + c0) = q2.C1;
                *reinterpret_cast<float4*>(sF + r0 * 20 + c0)       = q2.F0;
                if (lane < 16) {
                    const int r1 = 8 + (lane >> 2);
                    *reinterpret_cast<float4*>(sF + r1 * 20 + c0)   = q2.F1;
                }
                if (lane < 4) *reinterpret_cast<float4*>(sc_ + lane * 4) = q2.c4;
                if (lane < 3) reinterpret_cast<float4*>(sf_)[lane] = q2.f4;
            }
            __syncwarp();
            if (t < TT - 1) f_load(q2, gC, gc, gF, gf, (t + 1) * BB + b, lane);

            const float* sKt = sKall + t * 52;

            // controls: lane = a*4+u (lane<20)
            if (lane < 20) {
                const int a = lane >> 2, u = lane & 3;
                float ul = sKt[48 + u];
#pragma unroll
                for (int s = 0; s < 12; ++s) ul += sKt[s * 4 + u] * sX[a * 12 + s];
                const float alpha = 1.0f / (float)(1 << a);
                float uu = (1.0f - alpha) * sUn[t * 4 + u] + alpha * ul;
                uu = fminf(1.0f, fmaxf(-1.0f, uu));
                sTau[a * 16 + 12 + u] = uu;
            }
#pragma unroll
            for (int rr = 0; rr < 2; ++rr) {
                const int idx = lane + 32 * rr;
                if (idx < 60) {
                    const int a = idx / 12, s = idx - a * 12;
                    sTau[a * 16 + s] = sX[idx];
                }
            }
            __syncwarp();

            // cost partials (C symmetric: row read, stride 20) + taus writes
#pragma unroll
            for (int rr = 0; rr < 3; ++rr) {
                const int idx = lane + 32 * rr;
                if (idx < 80) {
                    const int a = idx >> 4, jj = idx & 15;
                    const float4* cr = reinterpret_cast<const float4*>(sC + jj * 20);
                    const float4* tr = reinterpret_cast<const float4*>(sTau + a * 16);
                    float s = 0.f;
#pragma unroll
                    for (int iv = 0; iv < 4; ++iv) {
                        const float4 cc = cr[iv], tt = tr[iv];
                        s += cc.x*tt.x + cc.y*tt.y + cc.z*tt.z + cc.w*tt.w;
                    }
                    const float ta = sTau[a * 16 + jj];
                    sPart[idx] = ta * (0.5f * s + sc_[jj]);
                    if (final_it || jj >= 12)
                        g_taus[((size_t)(a * TT + t) * BB + b) * 16 + jj] = ta;
                }
            }
            // x_next
            float xn0 = 0.f, xn1 = 0.f;
            {
                int idx = lane;
                if (idx < 60) {
                    const int a = idx / 12, s = idx - a * 12;
                    const float4* fr4 = reinterpret_cast<const float4*>(sF + s * 20);
                    const float4* tr  = reinterpret_cast<const float4*>(sTau + a * 16);
                    float v = sf_[s];
#pragma unroll
                    for (int iv = 0; iv < 4; ++iv) {
                        const float4 ff = fr4[iv], tt = tr[iv];
                        v += ff.x*tt.x + ff.y*tt.y + ff.z*tt.z + ff.w*tt.w;
                    }
                    xn0 = v;
                }
                idx = lane + 32;
                if (idx < 60) {
                    const int a = idx / 12, s = idx - a * 12;
                    const float4* fr4 = reinterpret_cast<const float4*>(sF + s * 20);
                    const float4* tr  = reinterpret_cast<const float4*>(sTau + a * 16);
                    float v = sf_[s];
#pragma unroll
                    for (int iv = 0; iv < 4; ++iv) {
                        const float4 ff = fr4[iv], tt = tr[iv];
                        v += ff.x*tt.x + ff.y*tt.y + ff.z*tt.z + ff.w*tt.w;
                    }
                    xn1 = v;
                }
            }
            __syncwarp();

            if (lane < 5) {
                const float4* pr = reinterpret_cast<const float4*>(sPart + lane * 16);
                float cs = 0.f;
#pragma unroll
                for (int iv = 0; iv < 4; ++iv) {
                    const float4 pp = pr[iv];
                    cs += pp.x + pp.y + pp.z + pp.w;
                }
                myCost += cs;
            }
            if (lane < 60) sX[lane] = xn0;
            if (lane + 32 < 60) sX[lane + 32] = xn1;
            __syncwarp();
        }

        // argmin over alphas (first-min)
        int bi = 0;
        {
            float bc = __shfl_sync(0xffffffffu, myCost, 0);
#pragma unroll
            for (int a = 1; a < NLS; ++a) {
                const float ca = __shfl_sync(0xffffffffu, myCost, a);
                if (ca < bc) { bc = ca; bi = a; }
            }
        }

        if (!final_it) {
            for (int idx = lane; idx < 200; idx += 32) {
                const int t = idx >> 2, u = idx & 3;
                sUn[idx] = g_taus[((size_t)(bi * TT + t) * BB + b) * 16 + 12 + u];
            }
        } else {
            for (int idx = lane; idx < 800; idx += 32) {
                const int t = idx >> 4, i = idx & 15;
                out[((size_t)t * BB + b) * 16 + i] =
                    g_taus[((size_t)(bi * TT + t) * BB + b) * 16 + i];
            }
        }
        __syncwarp();
    }
}

extern "C" void kernel_launch(void* const* d_in, const int* in_sizes, int n_in,
                              void* d_out, int out_size)
{
    const float *x0 = nullptr, *C = nullptr, *c = nullptr, *F = nullptr, *f = nullptr;
    for (int i = 0; i < n_in; ++i) {
        switch (in_sizes[i]) {
            case BB * 12:       x0 = (const float*)d_in[i]; break;
            case TT * BB * 256: C  = (const float*)d_in[i]; break;
            case TT * BB * 16:  c  = (const float*)d_in[i]; break;
            case TT * BB * 192: F  = (const float*)d_in[i]; break;
            case TT * BB * 12:  f  = (const float*)d_in[i]; break;
        }
    }
    ilqr_fused_kernel<<<BB / WPB, 32 * WPB>>>(C, c, F, f, x0, (float*)d_out);
}